// round 4
// baseline (speedup 1.0000x reference)
#include <cuda_runtime.h>
#include <cstdint>

#define BSZ   8
#define NSEQ  2048
#define EDIM  128
#define HEADS 4
#define DHEAD 32
#define NEGV  -1e9f
#define QSCALE 0.17677669529663687f  // 1/sqrt(32)

// Scratch: q/k/v stored PRE-CONVERTED to tf32 (q also pre-scaled)
__device__ unsigned g_q[(size_t)BSZ * HEADS * NSEQ * DHEAD];
__device__ unsigned g_k[(size_t)BSZ * HEADS * NSEQ * DHEAD];
__device__ unsigned g_v[(size_t)BSZ * HEADS * NSEQ * DHEAD];
__device__ float    g_attn[(size_t)BSZ * NSEQ * EDIM];
__device__ unsigned g_mask[(size_t)NSEQ * (NSEQ / 32)];   // adj[0] bit-packed

// --------------------------------------------------------------------------
__device__ __forceinline__ unsigned f2tf(float f) {
    unsigned r;
    asm("cvt.rna.tf32.f32 %0, %1;" : "=r"(r) : "f"(f));
    return r;
}

__device__ __forceinline__ void mma8(float* c,
                                     unsigned a0, unsigned a1, unsigned a2, unsigned a3,
                                     unsigned b0, unsigned b1) {
    asm volatile(
        "mma.sync.aligned.m16n8k8.row.col.f32.tf32.tf32.f32 "
        "{%0,%1,%2,%3}, {%4,%5,%6,%7}, {%8,%9}, {%0,%1,%2,%3};"
        : "+f"(c[0]), "+f"(c[1]), "+f"(c[2]), "+f"(c[3])
        : "r"(a0), "r"(a1), "r"(a2), "r"(a3), "r"(b0), "r"(b1));
}

__device__ __forceinline__ void cpa16(unsigned* dst, const unsigned* src) {
    unsigned d = (unsigned)__cvta_generic_to_shared(dst);
    asm volatile("cp.async.ca.shared.global [%0], [%1], 16;" :: "r"(d), "l"(src));
}

// --------------------------------------------------------------------------
// Kernel 0: bit-pack adj[0]
// --------------------------------------------------------------------------
__global__ __launch_bounds__(256) void maskpack_kernel(const int* __restrict__ adj) {
    int gid  = blockIdx.x * 256 + threadIdx.x;
    int w    = gid >> 5;
    int lane = gid & 31;
    int n    = w >> 6;
    int word = w & 63;
    int v = adj[(size_t)n * NSEQ + word * 32 + lane];
    unsigned m = __ballot_sync(0xffffffffu, v != 0);
    if (lane == 0) g_mask[w] = m;
}

// --------------------------------------------------------------------------
// Kernel 1: QKV projection (tf32 mma), 128 thr, tile 64 x 64.
// Outputs q (scaled) / k / v already converted to tf32, (B*H, N, D) layout.
// --------------------------------------------------------------------------
__global__ __launch_bounds__(128) void qkv_proj_kernel(
    const float* __restrict__ x, const float* __restrict__ w,
    const float* __restrict__ bias)
{
    __shared__ unsigned Xs[64 * 36];
    __shared__ unsigned Ws[64 * 36];

    const int tid = threadIdx.x;
    const int wp = tid >> 5, lane = tid & 31;
    const int g = lane >> 2, t = lane & 3;
    const int m0 = blockIdx.y * 64, c0 = blockIdx.x * 64;

    float acc[8][4];
    #pragma unroll
    for (int nt = 0; nt < 8; nt++)
        #pragma unroll
        for (int j = 0; j < 4; j++) acc[nt][j] = 0.f;

    for (int ko = 0; ko < EDIM; ko += 32) {
        __syncthreads();
        #pragma unroll
        for (int i = tid; i < 512; i += 128) {
            int r = i >> 3, c4 = (i & 7) * 4;
            float4 v4 = *(const float4*)&x[(size_t)(m0 + r) * EDIM + ko + c4];
            *(uint4*)&Xs[r * 36 + c4] =
                make_uint4(f2tf(v4.x), f2tf(v4.y), f2tf(v4.z), f2tf(v4.w));
            float4 w4 = *(const float4*)&w[(size_t)(c0 + r) * EDIM + ko + c4];
            *(uint4*)&Ws[r * 36 + c4] =
                make_uint4(f2tf(w4.x), f2tf(w4.y), f2tf(w4.z), f2tf(w4.w));
        }
        __syncthreads();

        #pragma unroll
        for (int kc = 0; kc < 4; kc++) {
            const unsigned* xr = &Xs[(wp * 16 + g) * 36 + kc * 8 + t];
            unsigned a0 = xr[0], a1 = xr[8 * 36], a2 = xr[4], a3 = xr[8 * 36 + 4];
            #pragma unroll
            for (int nt = 0; nt < 8; nt++) {
                unsigned b0 = Ws[(nt * 8 + g) * 36 + kc * 8 + t];
                unsigned b1 = Ws[(nt * 8 + g) * 36 + kc * 8 + t + 4];
                mma8(acc[nt], a0, a1, a2, a3, b0, b1);
            }
        }
    }

    const int mrow0 = m0 + wp * 16 + g;
    #pragma unroll
    for (int nt = 0; nt < 8; nt++) {
        int cg = c0 + nt * 8 + 2 * t;
        float b0v = bias[cg], b1v = bias[cg + 1];
        int part = cg >> 7;
        int e = cg & 127, h = e >> 5, d = e & 31;
        unsigned* base = (part == 0) ? g_q : (part == 1) ? g_k : g_v;
        float sc = (part == 0) ? QSCALE : 1.0f;
        #pragma unroll
        for (int rr = 0; rr < 2; rr++) {
            int m = mrow0 + rr * 8;
            int bb = m >> 11, n = m & (NSEQ - 1);
            float v0 = (acc[nt][rr * 2 + 0] + b0v) * sc;
            float v1 = (acc[nt][rr * 2 + 1] + b1v) * sc;
            *(uint2*)&base[(((size_t)bb * HEADS + h) * NSEQ + n) * DHEAD + d] =
                make_uint2(f2tf(v0), f2tf(v1));
        }
    }
}

// --------------------------------------------------------------------------
// Kernel 2: flash attention.  256 thr (8 warps), 128 q rows/block,
// 64 kv/iter, double-buffered cp.async K/V staging (pre-converted tf32).
// K pitch 36 (bank 4g+t), V pitch 40 (bank 8t+g) — both conflict-free.
// --------------------------------------------------------------------------
#define KP 36
#define VP 40
#define KT_WORDS (64 * KP)   // 2304
#define VT_WORDS (64 * VP)   // 2560
#define PT_WORDS (16 * 68)   // 1088 per warp
#define ATTN_SMEM_BYTES ((2 * KT_WORDS + 2 * VT_WORDS + 8 * PT_WORDS) * 4)

__device__ __forceinline__ void stage_kv(unsigned* kd, unsigned* vd,
                                         const unsigned* ks, const unsigned* vs,
                                         int tid) {
    #pragma unroll
    for (int i = tid; i < 512; i += 256) {
        int r = i >> 3, c = (i & 7) * 4;
        cpa16(&kd[r * KP + c], &ks[r * 32 + c]);
        cpa16(&vd[r * VP + c], &vs[r * 32 + c]);
    }
    asm volatile("cp.async.commit_group;");
}

__global__ __launch_bounds__(256) void attn_kernel()
{
    extern __shared__ unsigned sm[];
    unsigned* Kb = sm;                       // [2][KT_WORDS]
    unsigned* Vb = sm + 2 * KT_WORDS;        // [2][VT_WORDS]
    unsigned* Pall = sm + 2 * KT_WORDS + 2 * VT_WORDS;  // [8][PT_WORDS]

    const int tid = threadIdx.x;
    const int wp = tid >> 5, lane = tid & 31;
    const int g = lane >> 2, t = lane & 3;
    const int qt = blockIdx.x, bh = blockIdx.y;

    const size_t qkv_off = (size_t)bh * NSEQ * DHEAD;
    const int r0 = qt * 128 + wp * 16 + g;
    const int r1 = r0 + 8;

    // Q fragments (already tf32 + scaled)
    unsigned qa[4][4];
    {
        const unsigned* q0 = g_q + qkv_off + (size_t)r0 * DHEAD;
        const unsigned* q1 = g_q + qkv_off + (size_t)r1 * DHEAD;
        #pragma unroll
        for (int kc = 0; kc < 4; kc++) {
            qa[kc][0] = q0[kc * 8 + t];
            qa[kc][1] = q1[kc * 8 + t];
            qa[kc][2] = q0[kc * 8 + t + 4];
            qa[kc][3] = q1[kc * 8 + t + 4];
        }
    }

    float o[4][4];
    #pragma unroll
    for (int nt = 0; nt < 4; nt++)
        #pragma unroll
        for (int j = 0; j < 4; j++) o[nt][j] = 0.f;

    float m0v = -1e30f, m1v = -1e30f, l0 = 0.f, l1 = 0.f;

    const unsigned* mrow0 = &g_mask[(size_t)r0 * 64];
    const unsigned* mrow1 = &g_mask[(size_t)r1 * 64];
    unsigned* Pw = Pall + wp * PT_WORDS;

    const unsigned* kbase = g_k + qkv_off;
    const unsigned* vbase = g_v + qkv_off;

    // prologue: stage tile 0 into buffer 0
    stage_kv(Kb, Vb, kbase, vbase, tid);

    for (int kt = 0; kt < NSEQ / 64; kt++) {
        const int cur = kt & 1;
        if (kt + 1 < NSEQ / 64) {
            stage_kv(Kb + (cur ^ 1) * KT_WORDS, Vb + (cur ^ 1) * VT_WORDS,
                     kbase + (size_t)(kt + 1) * 64 * DHEAD,
                     vbase + (size_t)(kt + 1) * 64 * DHEAD, tid);
            asm volatile("cp.async.wait_group 1;");
        } else {
            asm volatile("cp.async.wait_group 0;");
        }
        __syncthreads();

        const unsigned* Ks = Kb + cur * KT_WORDS;
        const unsigned* Vs = Vb + cur * VT_WORDS;

        // S = Q K^T  (16 x 64 per warp)
        float s[8][4] = {};
        #pragma unroll
        for (int kc = 0; kc < 4; kc++) {
            #pragma unroll
            for (int nt = 0; nt < 8; nt++) {
                unsigned b0 = Ks[(nt * 8 + g) * KP + kc * 8 + t];
                unsigned b1 = Ks[(nt * 8 + g) * KP + kc * 8 + t + 4];
                mma8(s[nt], qa[kc][0], qa[kc][1], qa[kc][2], qa[kc][3], b0, b1);
            }
        }

        // additive mask from packed bits
        uint2 mw0 = *(const uint2*)&mrow0[kt * 2];
        uint2 mw1 = *(const uint2*)&mrow1[kt * 2];
        #pragma unroll
        for (int nt = 0; nt < 8; nt++) {
            int sh = (nt * 8 + 2 * t) & 31;
            unsigned w0 = (nt < 4) ? mw0.x : mw0.y;
            unsigned w1 = (nt < 4) ? mw1.x : mw1.y;
            if (!((w0 >> sh) & 1))       s[nt][0] += NEGV;
            if (!((w0 >> (sh + 1)) & 1)) s[nt][1] += NEGV;
            if (!((w1 >> sh) & 1))       s[nt][2] += NEGV;
            if (!((w1 >> (sh + 1)) & 1)) s[nt][3] += NEGV;
        }

        // online softmax
        float rm0 = -1e30f, rm1 = -1e30f;
        #pragma unroll
        for (int nt = 0; nt < 8; nt++) {
            rm0 = fmaxf(rm0, fmaxf(s[nt][0], s[nt][1]));
            rm1 = fmaxf(rm1, fmaxf(s[nt][2], s[nt][3]));
        }
        rm0 = fmaxf(rm0, __shfl_xor_sync(0xffffffffu, rm0, 1));
        rm0 = fmaxf(rm0, __shfl_xor_sync(0xffffffffu, rm0, 2));
        rm1 = fmaxf(rm1, __shfl_xor_sync(0xffffffffu, rm1, 1));
        rm1 = fmaxf(rm1, __shfl_xor_sync(0xffffffffu, rm1, 2));

        float mn0 = fmaxf(m0v, rm0), mn1 = fmaxf(m1v, rm1);
        float al0 = __expf(m0v - mn0), al1 = __expf(m1v - mn1);
        m0v = mn0; m1v = mn1;

        float ps0 = 0.f, ps1 = 0.f;
        #pragma unroll
        for (int nt = 0; nt < 8; nt++) {
            float p0 = __expf(s[nt][0] - mn0);
            float p1 = __expf(s[nt][1] - mn0);
            float p2 = __expf(s[nt][2] - mn1);
            float p3 = __expf(s[nt][3] - mn1);
            ps0 += p0 + p1;
            ps1 += p2 + p3;
            int c = nt * 8 + 2 * t;
            *(uint2*)&Pw[g * 68 + c]       = make_uint2(f2tf(p0), f2tf(p1));
            *(uint2*)&Pw[(g + 8) * 68 + c] = make_uint2(f2tf(p2), f2tf(p3));
        }
        l0 = l0 * al0 + ps0;
        l1 = l1 * al1 + ps1;
        #pragma unroll
        for (int nt = 0; nt < 4; nt++) {
            o[nt][0] *= al0; o[nt][1] *= al0;
            o[nt][2] *= al1; o[nt][3] *= al1;
        }
        __syncwarp();

        // O += P @ V
        #pragma unroll
        for (int kc = 0; kc < 8; kc++) {
            unsigned pa0 = Pw[g * 68 + kc * 8 + t];
            unsigned pa1 = Pw[(g + 8) * 68 + kc * 8 + t];
            unsigned pa2 = Pw[g * 68 + kc * 8 + t + 4];
            unsigned pa3 = Pw[(g + 8) * 68 + kc * 8 + t + 4];
            #pragma unroll
            for (int nt = 0; nt < 4; nt++) {
                unsigned vb0 = Vs[(kc * 8 + t) * VP + nt * 8 + g];
                unsigned vb1 = Vs[(kc * 8 + t + 4) * VP + nt * 8 + g];
                mma8(o[nt], pa0, pa1, pa2, pa3, vb0, vb1);
            }
        }
        __syncthreads();   // all warps done with this buffer before reuse
    }

    // epilogue
    l0 += __shfl_xor_sync(0xffffffffu, l0, 1);
    l0 += __shfl_xor_sync(0xffffffffu, l0, 2);
    l1 += __shfl_xor_sync(0xffffffffu, l1, 1);
    l1 += __shfl_xor_sync(0xffffffffu, l1, 2);
    float inv0 = 1.f / l0, inv1 = 1.f / l1;

    const int b = bh >> 2, h = bh & 3;
    float* d0 = g_attn + ((size_t)b * NSEQ + r0) * EDIM + h * DHEAD;
    float* d1 = g_attn + ((size_t)b * NSEQ + r1) * EDIM + h * DHEAD;
    #pragma unroll
    for (int nt = 0; nt < 4; nt++) {
        int c = nt * 8 + 2 * t;
        *(float2*)&d0[c] = make_float2(o[nt][0] * inv0, o[nt][1] * inv0);
        *(float2*)&d1[c] = make_float2(o[nt][2] * inv1, o[nt][3] * inv1);
    }
}

// --------------------------------------------------------------------------
// Kernel 3: output projection, 128 thr, tile 64 x 64.
// --------------------------------------------------------------------------
__global__ __launch_bounds__(128) void out_proj_kernel(
    const float* __restrict__ w, const float* __restrict__ bias,
    float* __restrict__ out)
{
    __shared__ unsigned Xs[64 * 36];
    __shared__ unsigned Ws[64 * 36];

    const int tid = threadIdx.x;
    const int wp = tid >> 5, lane = tid & 31;
    const int g = lane >> 2, t = lane & 3;
    const int m0 = blockIdx.y * 64, c0 = blockIdx.x * 64;

    float acc[8][4];
    #pragma unroll
    for (int nt = 0; nt < 8; nt++)
        #pragma unroll
        for (int j = 0; j < 4; j++) acc[nt][j] = 0.f;

    for (int ko = 0; ko < EDIM; ko += 32) {
        __syncthreads();
        #pragma unroll
        for (int i = tid; i < 512; i += 128) {
            int r = i >> 3, c4 = (i & 7) * 4;
            float4 v4 = *(const float4*)&g_attn[(size_t)(m0 + r) * EDIM + ko + c4];
            *(uint4*)&Xs[r * 36 + c4] =
                make_uint4(f2tf(v4.x), f2tf(v4.y), f2tf(v4.z), f2tf(v4.w));
            float4 w4 = *(const float4*)&w[(size_t)(c0 + r) * EDIM + ko + c4];
            *(uint4*)&Ws[r * 36 + c4] =
                make_uint4(f2tf(w4.x), f2tf(w4.y), f2tf(w4.z), f2tf(w4.w));
        }
        __syncthreads();

        #pragma unroll
        for (int kc = 0; kc < 4; kc++) {
            const unsigned* xr = &Xs[(wp * 16 + g) * 36 + kc * 8 + t];
            unsigned a0 = xr[0], a1 = xr[8 * 36], a2 = xr[4], a3 = xr[8 * 36 + 4];
            #pragma unroll
            for (int nt = 0; nt < 8; nt++) {
                unsigned b0 = Ws[(nt * 8 + g) * 36 + kc * 8 + t];
                unsigned b1 = Ws[(nt * 8 + g) * 36 + kc * 8 + t + 4];
                mma8(acc[nt], a0, a1, a2, a3, b0, b1);
            }
        }
    }

    const int mrow0 = m0 + wp * 16 + g;
    #pragma unroll
    for (int nt = 0; nt < 8; nt++) {
        int cg = c0 + nt * 8 + 2 * t;
        float b0v = bias[cg], b1v = bias[cg + 1];
        #pragma unroll
        for (int rr = 0; rr < 2; rr++) {
            int m = mrow0 + rr * 8;
            *(float2*)&out[(size_t)m * EDIM + cg] =
                make_float2(acc[nt][rr * 2 + 0] + b0v, acc[nt][rr * 2 + 1] + b1v);
        }
    }
}

// --------------------------------------------------------------------------
extern "C" void kernel_launch(void* const* d_in, const int* in_sizes, int n_in,
                              void* d_out, int out_size)
{
    const float* x   = (const float*)d_in[0];
    const int*   adj = (const int*)  d_in[1];
    const float* ipw = (const float*)d_in[2];
    const float* ipb = (const float*)d_in[3];
    const float* ow  = (const float*)d_in[4];
    const float* ob  = (const float*)d_in[5];
    float* out = (float*)d_out;

    (void)in_sizes; (void)n_in; (void)out_size;

    // allow >48KB dynamic smem for attention (idempotent, capture-safe)
    cudaFuncSetAttribute(attn_kernel,
                         cudaFuncAttributeMaxDynamicSharedMemorySize,
                         ATTN_SMEM_BYTES);

    maskpack_kernel<<<16384, 256>>>(adj);
    qkv_proj_kernel<<<dim3(6, 256), 128>>>(x, ipw, ipb);
    attn_kernel<<<dim3(16, 32), 256, ATTN_SMEM_BYTES>>>();
    out_proj_kernel<<<dim3(2, 256), 128>>>(ow, ob, out);
}

// round 5
// speedup vs baseline: 1.7373x; 1.7373x over previous
#include <cuda_runtime.h>
#include <cuda_fp16.h>
#include <cstdint>

#define BSZ   8
#define NSEQ  2048
#define EDIM  128
#define HEADS 4
#define DHEAD 32
#define NEGV  -1e9f
#define QSCALE 0.17677669529663687f          // 1/sqrt(32)
#define QS2    0.25503482120645087f          // (1/sqrt(32)) * log2(e)

// Scratch: q/k packed half2 words [bh][n][16], v transposed half [bh][d][n]
__device__ unsigned g_qw[(size_t)BSZ * HEADS * NSEQ * (DHEAD / 2)];
__device__ unsigned g_kw[(size_t)BSZ * HEADS * NSEQ * (DHEAD / 2)];
__device__ __half   g_vt[(size_t)BSZ * HEADS * DHEAD * NSEQ];
__device__ float    g_attn[(size_t)BSZ * NSEQ * EDIM];
__device__ unsigned g_mask[(size_t)NSEQ * (NSEQ / 32)];

// --------------------------------------------------------------------------
__device__ __forceinline__ unsigned f2tf(float f) {
    unsigned r;
    asm("cvt.rna.tf32.f32 %0, %1;" : "=r"(r) : "f"(f));
    return r;
}
__device__ __forceinline__ float fexp2(float x) {
    float r;
    asm("ex2.approx.f32 %0, %1;" : "=f"(r) : "f"(x));
    return r;
}
__device__ __forceinline__ unsigned packh2(float a, float b) {
    __half2 h = __floats2half2_rn(a, b);   // low = a, high = b
    return *(unsigned*)&h;
}
// tf32 m16n8k8 (projections)
__device__ __forceinline__ void mma8(float* c,
                                     unsigned a0, unsigned a1, unsigned a2, unsigned a3,
                                     unsigned b0, unsigned b1) {
    asm volatile(
        "mma.sync.aligned.m16n8k8.row.col.f32.tf32.tf32.f32 "
        "{%0,%1,%2,%3}, {%4,%5,%6,%7}, {%8,%9}, {%0,%1,%2,%3};"
        : "+f"(c[0]), "+f"(c[1]), "+f"(c[2]), "+f"(c[3])
        : "r"(a0), "r"(a1), "r"(a2), "r"(a3), "r"(b0), "r"(b1));
}
// fp16 m16n8k16, fp32 accumulate (attention)
__device__ __forceinline__ void mma16(float* c,
                                      unsigned a0, unsigned a1, unsigned a2, unsigned a3,
                                      unsigned b0, unsigned b1) {
    asm volatile(
        "mma.sync.aligned.m16n8k16.row.col.f32.f16.f16.f32 "
        "{%0,%1,%2,%3}, {%4,%5,%6,%7}, {%8,%9}, {%0,%1,%2,%3};"
        : "+f"(c[0]), "+f"(c[1]), "+f"(c[2]), "+f"(c[3])
        : "r"(a0), "r"(a1), "r"(a2), "r"(a3), "r"(b0), "r"(b1));
}
__device__ __forceinline__ void cpa16(unsigned* dst, const unsigned* src) {
    unsigned d = (unsigned)__cvta_generic_to_shared(dst);
    asm volatile("cp.async.ca.shared.global [%0], [%1], 16;" :: "r"(d), "l"(src));
}

// --------------------------------------------------------------------------
// Kernel 0: bit-pack adj[0]
// --------------------------------------------------------------------------
__global__ __launch_bounds__(256) void maskpack_kernel(const int* __restrict__ adj) {
    int gid  = blockIdx.x * 256 + threadIdx.x;
    int w    = gid >> 5;
    int lane = gid & 31;
    int n    = w >> 6;
    int word = w & 63;
    int v = adj[(size_t)n * NSEQ + word * 32 + lane];
    unsigned m = __ballot_sync(0xffffffffu, v != 0);
    if (lane == 0) g_mask[w] = m;
}

// --------------------------------------------------------------------------
// Kernel 1: QKV projection (tf32 mma), 256 thr, tile 128 x 64.
// Writes q (scaled by QS2) / k as packed half2, v transposed as half.
// --------------------------------------------------------------------------
__global__ __launch_bounds__(256) void qkv_proj_kernel(
    const float* __restrict__ x, const float* __restrict__ w,
    const float* __restrict__ bias)
{
    __shared__ unsigned Xs[128 * 36];
    __shared__ unsigned Ws[64 * 36];

    const int tid = threadIdx.x;
    const int wp = tid >> 5, lane = tid & 31;
    const int g = lane >> 2, t = lane & 3;
    const int m0 = blockIdx.y * 128, c0 = blockIdx.x * 64;

    float acc[8][4];
    #pragma unroll
    for (int nt = 0; nt < 8; nt++)
        #pragma unroll
        for (int j = 0; j < 4; j++) acc[nt][j] = 0.f;

    for (int ko = 0; ko < EDIM; ko += 32) {
        __syncthreads();
        #pragma unroll
        for (int i = tid; i < 1024; i += 256) {
            int r = i >> 3, c4 = (i & 7) * 4;
            float4 v4 = *(const float4*)&x[(size_t)(m0 + r) * EDIM + ko + c4];
            *(uint4*)&Xs[r * 36 + c4] =
                make_uint4(f2tf(v4.x), f2tf(v4.y), f2tf(v4.z), f2tf(v4.w));
        }
        #pragma unroll
        for (int i = tid; i < 512; i += 256) {
            int r = i >> 3, c4 = (i & 7) * 4;
            float4 w4 = *(const float4*)&w[(size_t)(c0 + r) * EDIM + ko + c4];
            *(uint4*)&Ws[r * 36 + c4] =
                make_uint4(f2tf(w4.x), f2tf(w4.y), f2tf(w4.z), f2tf(w4.w));
        }
        __syncthreads();

        #pragma unroll
        for (int kc = 0; kc < 4; kc++) {
            const unsigned* xr = &Xs[(wp * 16 + g) * 36 + kc * 8 + t];
            unsigned a0 = xr[0], a1 = xr[8 * 36], a2 = xr[4], a3 = xr[8 * 36 + 4];
            #pragma unroll
            for (int nt = 0; nt < 8; nt++) {
                unsigned b0 = Ws[(nt * 8 + g) * 36 + kc * 8 + t];
                unsigned b1 = Ws[(nt * 8 + g) * 36 + kc * 8 + t + 4];
                mma8(acc[nt], a0, a1, a2, a3, b0, b1);
            }
        }
    }

    const int mrow0 = m0 + wp * 16 + g;
    #pragma unroll
    for (int nt = 0; nt < 8; nt++) {
        int cg = c0 + nt * 8 + 2 * t;
        float b0v = bias[cg], b1v = bias[cg + 1];
        int part = cg >> 7;
        int e = cg & 127, hh = e >> 5, d0 = e & 31;
        #pragma unroll
        for (int rr = 0; rr < 2; rr++) {
            int m = mrow0 + rr * 8;
            int bb = m >> 11, n = m & (NSEQ - 1);
            int bh = bb * HEADS + hh;
            float v0 = acc[nt][rr * 2 + 0] + b0v;
            float v1 = acc[nt][rr * 2 + 1] + b1v;
            if (part == 0) {
                g_qw[((size_t)bh * NSEQ + n) * 16 + (d0 >> 1)] =
                    packh2(v0 * QS2, v1 * QS2);
            } else if (part == 1) {
                g_kw[((size_t)bh * NSEQ + n) * 16 + (d0 >> 1)] = packh2(v0, v1);
            } else {
                g_vt[((size_t)bh * DHEAD + d0)     * NSEQ + n] = __float2half_rn(v0);
                g_vt[((size_t)bh * DHEAD + d0 + 1) * NSEQ + n] = __float2half_rn(v1);
            }
        }
    }
}

// --------------------------------------------------------------------------
// Kernel 2: flash attention, fp16 mma m16n8k16.  128 thr (4 warps),
// 64 q rows/block, 64 kv/iter, double-buffered cp.async K/Vt staging.
// P stays entirely in registers (QK C-layout == PV A-layout when half2-packed).
// --------------------------------------------------------------------------
#define KPW 20                 // K smem pitch (words; 16 data)
#define VPW 36                 // Vt smem pitch (words; 32 data)
#define KT_W (64 * KPW)        // 1280 words
#define VT_W (32 * VPW)        // 1152 words

__device__ __forceinline__ void stage_kv(unsigned* kd, unsigned* vd,
                                         const unsigned* kg, const unsigned* vg,
                                         int tid) {
    // K tile: 64 rows x 16 words (contiguous).  Vt tile: 32 rows x 32 words,
    // global row stride 1024 words.
    #pragma unroll
    for (int i = tid; i < 512; i += 128) {
        if (i < 256) {
            int r = i >> 2, c = (i & 3) * 4;
            cpa16(&kd[r * KPW + c], &kg[r * 16 + c]);
        } else {
            int j = i - 256;
            int r = j >> 3, c = (j & 7) * 4;
            cpa16(&vd[r * VPW + c], &vg[(size_t)r * (NSEQ / 2) + c]);
        }
    }
    asm volatile("cp.async.commit_group;" ::: "memory");
}

__global__ __launch_bounds__(128) void attn_kernel()
{
    __shared__ unsigned Kb[2 * KT_W];
    __shared__ unsigned Vb[2 * VT_W];

    const int tid = threadIdx.x;
    const int wp = tid >> 5, lane = tid & 31;
    const int g = lane >> 2, t = lane & 3;
    const int qt = blockIdx.x, bh = blockIdx.y;

    const int r0 = qt * 64 + wp * 16 + g;
    const int r1 = r0 + 8;

    // Q fragments (half2 words, pre-scaled by QS2)
    unsigned qa[2][4];
    {
        const unsigned* q0 = g_qw + ((size_t)bh * NSEQ + r0) * 16;
        const unsigned* q1 = g_qw + ((size_t)bh * NSEQ + r1) * 16;
        #pragma unroll
        for (int kc = 0; kc < 2; kc++) {
            qa[kc][0] = q0[kc * 8 + t];
            qa[kc][1] = q1[kc * 8 + t];
            qa[kc][2] = q0[kc * 8 + t + 4];
            qa[kc][3] = q1[kc * 8 + t + 4];
        }
    }

    float o[4][4];
    #pragma unroll
    for (int nt = 0; nt < 4; nt++)
        #pragma unroll
        for (int j = 0; j < 4; j++) o[nt][j] = 0.f;

    float m0v = -1e30f, m1v = -1e30f, l0 = 0.f, l1 = 0.f;

    const unsigned* mrow0 = &g_mask[(size_t)r0 * 64];
    const unsigned* mrow1 = &g_mask[(size_t)r1 * 64];

    const unsigned* kbase = g_kw + (size_t)bh * NSEQ * 16;
    const unsigned* vbase = (const unsigned*)g_vt + (size_t)bh * DHEAD * (NSEQ / 2);

    stage_kv(Kb, Vb, kbase, vbase, tid);

    for (int kt = 0; kt < NSEQ / 64; kt++) {
        const int cur = kt & 1;
        if (kt + 1 < NSEQ / 64) {
            stage_kv(Kb + (cur ^ 1) * KT_W, Vb + (cur ^ 1) * VT_W,
                     kbase + (size_t)(kt + 1) * 64 * 16,
                     vbase + (size_t)(kt + 1) * 32, tid);
            asm volatile("cp.async.wait_group 1;" ::: "memory");
        } else {
            asm volatile("cp.async.wait_group 0;" ::: "memory");
        }
        __syncthreads();

        const unsigned* Ks = Kb + cur * KT_W;
        const unsigned* Vs = Vb + cur * VT_W;

        // S = Q K^T  (16 x 64 per warp): 2 kc blocks x 8 n-blocks
        float s[8][4] = {};
        #pragma unroll
        for (int kc = 0; kc < 2; kc++) {
            #pragma unroll
            for (int nt = 0; nt < 8; nt++) {
                unsigned b0 = Ks[(nt * 8 + g) * KPW + kc * 8 + t];
                unsigned b1 = Ks[(nt * 8 + g) * KPW + kc * 8 + t + 4];
                mma16(s[nt], qa[kc][0], qa[kc][1], qa[kc][2], qa[kc][3], b0, b1);
            }
        }

        // additive mask
        uint2 mw0 = *(const uint2*)&mrow0[kt * 2];
        uint2 mw1 = *(const uint2*)&mrow1[kt * 2];
        #pragma unroll
        for (int nt = 0; nt < 8; nt++) {
            int sh = (nt * 8 + 2 * t) & 31;
            unsigned w0 = (nt < 4) ? mw0.x : mw0.y;
            unsigned w1 = (nt < 4) ? mw1.x : mw1.y;
            if (!((w0 >> sh) & 1))       s[nt][0] += NEGV;
            if (!((w0 >> (sh + 1)) & 1)) s[nt][1] += NEGV;
            if (!((w1 >> sh) & 1))       s[nt][2] += NEGV;
            if (!((w1 >> (sh + 1)) & 1)) s[nt][3] += NEGV;
        }

        // online softmax (log2 domain; Q pre-scaled by log2(e)/sqrt(d))
        float rm0 = -1e30f, rm1 = -1e30f;
        #pragma unroll
        for (int nt = 0; nt < 8; nt++) {
            rm0 = fmaxf(rm0, fmaxf(s[nt][0], s[nt][1]));
            rm1 = fmaxf(rm1, fmaxf(s[nt][2], s[nt][3]));
        }
        rm0 = fmaxf(rm0, __shfl_xor_sync(0xffffffffu, rm0, 1));
        rm0 = fmaxf(rm0, __shfl_xor_sync(0xffffffffu, rm0, 2));
        rm1 = fmaxf(rm1, __shfl_xor_sync(0xffffffffu, rm1, 1));
        rm1 = fmaxf(rm1, __shfl_xor_sync(0xffffffffu, rm1, 2));

        float mn0 = fmaxf(m0v, rm0), mn1 = fmaxf(m1v, rm1);
        float al0 = fexp2(m0v - mn0), al1 = fexp2(m1v - mn1);
        m0v = mn0; m1v = mn1;

        // P = exp2(S - m), packed straight into PV A-fragments (no SMEM)
        unsigned pa[4][4];
        float ps0 = 0.f, ps1 = 0.f;
        #pragma unroll
        for (int j = 0; j < 4; j++) {
            float p00 = fexp2(s[2*j][0]   - mn0), p01 = fexp2(s[2*j][1]   - mn0);
            float p10 = fexp2(s[2*j][2]   - mn1), p11 = fexp2(s[2*j][3]   - mn1);
            float p20 = fexp2(s[2*j+1][0] - mn0), p21 = fexp2(s[2*j+1][1] - mn0);
            float p30 = fexp2(s[2*j+1][2] - mn1), p31 = fexp2(s[2*j+1][3] - mn1);
            ps0 += (p00 + p01) + (p20 + p21);
            ps1 += (p10 + p11) + (p30 + p31);
            pa[j][0] = packh2(p00, p01);   // (row g,   kv 16j+2t..)
            pa[j][1] = packh2(p10, p11);   // (row g+8, kv 16j+2t..)
            pa[j][2] = packh2(p20, p21);   // (row g,   kv 16j+8+2t..)
            pa[j][3] = packh2(p30, p31);   // (row g+8, kv 16j+8+2t..)
        }
        l0 = l0 * al0 + ps0;
        l1 = l1 * al1 + ps1;
        #pragma unroll
        for (int nt = 0; nt < 4; nt++) {
            o[nt][0] *= al0; o[nt][1] *= al0;
            o[nt][2] *= al1; o[nt][3] *= al1;
        }

        // O += P @ V : 4 k-blocks x 4 d-blocks, B frags from transposed V
        #pragma unroll
        for (int j = 0; j < 4; j++) {
            #pragma unroll
            for (int nt = 0; nt < 4; nt++) {
                unsigned b0 = Vs[(nt * 8 + g) * VPW + j * 8 + t];
                unsigned b1 = Vs[(nt * 8 + g) * VPW + j * 8 + t + 4];
                mma16(o[nt], pa[j][0], pa[j][1], pa[j][2], pa[j][3], b0, b1);
            }
        }
        __syncthreads();   // all warps done with this buffer before restaging
    }

    // epilogue: reduce l over 4 lanes of row group, normalize, store
    l0 += __shfl_xor_sync(0xffffffffu, l0, 1);
    l0 += __shfl_xor_sync(0xffffffffu, l0, 2);
    l1 += __shfl_xor_sync(0xffffffffu, l1, 1);
    l1 += __shfl_xor_sync(0xffffffffu, l1, 2);
    float inv0 = 1.f / l0, inv1 = 1.f / l1;

    const int b = bh >> 2, h = bh & 3;
    float* d0 = g_attn + ((size_t)b * NSEQ + r0) * EDIM + h * DHEAD;
    float* d1 = g_attn + ((size_t)b * NSEQ + r1) * EDIM + h * DHEAD;
    #pragma unroll
    for (int nt = 0; nt < 4; nt++) {
        int c = nt * 8 + 2 * t;
        *(float2*)&d0[c] = make_float2(o[nt][0] * inv0, o[nt][1] * inv0);
        *(float2*)&d1[c] = make_float2(o[nt][2] * inv1, o[nt][3] * inv1);
    }
}

// --------------------------------------------------------------------------
// Kernel 3: output projection (tf32 mma), 256 thr, tile 128 x 64.
// --------------------------------------------------------------------------
__global__ __launch_bounds__(256) void out_proj_kernel(
    const float* __restrict__ w, const float* __restrict__ bias,
    float* __restrict__ out)
{
    __shared__ unsigned Xs[128 * 36];
    __shared__ unsigned Ws[64 * 36];

    const int tid = threadIdx.x;
    const int wp = tid >> 5, lane = tid & 31;
    const int g = lane >> 2, t = lane & 3;
    const int m0 = blockIdx.y * 128, c0 = blockIdx.x * 64;

    float acc[8][4];
    #pragma unroll
    for (int nt = 0; nt < 8; nt++)
        #pragma unroll
        for (int j = 0; j < 4; j++) acc[nt][j] = 0.f;

    for (int ko = 0; ko < EDIM; ko += 32) {
        __syncthreads();
        #pragma unroll
        for (int i = tid; i < 1024; i += 256) {
            int r = i >> 3, c4 = (i & 7) * 4;
            float4 v4 = *(const float4*)&g_attn[(size_t)(m0 + r) * EDIM + ko + c4];
            *(uint4*)&Xs[r * 36 + c4] =
                make_uint4(f2tf(v4.x), f2tf(v4.y), f2tf(v4.z), f2tf(v4.w));
        }
        #pragma unroll
        for (int i = tid; i < 512; i += 256) {
            int r = i >> 3, c4 = (i & 7) * 4;
            float4 w4 = *(const float4*)&w[(size_t)(c0 + r) * EDIM + ko + c4];
            *(uint4*)&Ws[r * 36 + c4] =
                make_uint4(f2tf(w4.x), f2tf(w4.y), f2tf(w4.z), f2tf(w4.w));
        }
        __syncthreads();

        #pragma unroll
        for (int kc = 0; kc < 4; kc++) {
            const unsigned* xr = &Xs[(wp * 16 + g) * 36 + kc * 8 + t];
            unsigned a0 = xr[0], a1 = xr[8 * 36], a2 = xr[4], a3 = xr[8 * 36 + 4];
            #pragma unroll
            for (int nt = 0; nt < 8; nt++) {
                unsigned b0 = Ws[(nt * 8 + g) * 36 + kc * 8 + t];
                unsigned b1 = Ws[(nt * 8 + g) * 36 + kc * 8 + t + 4];
                mma8(acc[nt], a0, a1, a2, a3, b0, b1);
            }
        }
    }

    const int mrow0 = m0 + wp * 16 + g;
    #pragma unroll
    for (int nt = 0; nt < 8; nt++) {
        int cg = c0 + nt * 8 + 2 * t;
        float b0v = bias[cg], b1v = bias[cg + 1];
        #pragma unroll
        for (int rr = 0; rr < 2; rr++) {
            int m = mrow0 + rr * 8;
            *(float2*)&out[(size_t)m * EDIM + cg] =
                make_float2(acc[nt][rr * 2 + 0] + b0v, acc[nt][rr * 2 + 1] + b1v);
        }
    }
}

// --------------------------------------------------------------------------
extern "C" void kernel_launch(void* const* d_in, const int* in_sizes, int n_in,
                              void* d_out, int out_size)
{
    const float* x   = (const float*)d_in[0];
    const int*   adj = (const int*)  d_in[1];
    const float* ipw = (const float*)d_in[2];
    const float* ipb = (const float*)d_in[3];
    const float* ow  = (const float*)d_in[4];
    const float* ob  = (const float*)d_in[5];
    float* out = (float*)d_out;

    (void)in_sizes; (void)n_in; (void)out_size;

    maskpack_kernel<<<16384, 256>>>(adj);
    qkv_proj_kernel<<<dim3(6, 128), 256>>>(x, ipw, ipb);
    attn_kernel<<<dim3(32, 32), 128>>>();
    out_proj_kernel<<<dim3(2, 128), 256>>>(ow, ob, out);
}